// round 9
// baseline (speedup 1.0000x reference)
#include <cuda_runtime.h>
#include <cuda_bf16.h>
#include <cstdint>

// ============================================================================
// ModelR: x[8192,1024] -> (Linear+LeakyReLU) x4 -> Linear -> tri-scatter
// Round 9: HMMA bf16 3-term split GEMM; BN 128->256 (warp tile 64x64),
// BK=64, 2-stage cp.async double buffer (221184B smem, 1 CTA/SM).
// Barriers per flop halved vs R8; ldsm per MMA down 1.5x; B traffic/flop 0.75x.
//   D = Ah*Bh + Ah*Bl + Al*Bh  (bf16 hi/lo split, fp32 accum, err ~2^-16)
// ============================================================================

#define BATCH 8192
#define DIN   1024
#define HID   2048
#define LOUT  2080
#define CPV   64

#define PITCH   144         // 128B payload (64 bf16) + 16B pad
#define OFF_AH  0
#define OFF_AL  18432       // 128 rows * 144B
#define OFF_BH  36864
#define OFF_BL  73728       // OFF_BH + 256 rows * 144B
#define STAGE   110592
#define NSTAGE  2
#define SMEMSZ  (NSTAGE * STAGE)   // 221184 B

// ------------------------- device scratch (no allocs) -----------------------
__device__ __nv_bfloat16 g_Ah0[(size_t)BATCH * HID];
__device__ __nv_bfloat16 g_Al0[(size_t)BATCH * HID];
__device__ __nv_bfloat16 g_Ah1[(size_t)BATCH * HID];
__device__ __nv_bfloat16 g_Al1[(size_t)BATCH * HID];
__device__ __nv_bfloat16 g_W1h[(size_t)HID * DIN];
__device__ __nv_bfloat16 g_W1l[(size_t)HID * DIN];
__device__ __nv_bfloat16 g_W2h[(size_t)HID * HID];
__device__ __nv_bfloat16 g_W2l[(size_t)HID * HID];
__device__ __nv_bfloat16 g_W21h[(size_t)HID * HID];
__device__ __nv_bfloat16 g_W21l[(size_t)HID * HID];
__device__ __nv_bfloat16 g_W22h[(size_t)HID * HID];
__device__ __nv_bfloat16 g_W22l[(size_t)HID * HID];
__device__ __nv_bfloat16 g_W3h[(size_t)LOUT * HID];
__device__ __nv_bfloat16 g_W3l[(size_t)LOUT * HID];
__device__ float         g_Y[(size_t)BATCH * LOUT];

// ------------------------------ PTX helpers ---------------------------------
__device__ __forceinline__ uint32_t smem_u32(const void* p) {
    uint32_t a;
    asm("{ .reg .u64 t; cvta.to.shared.u64 t, %1; cvt.u32.u64 %0, t; }"
        : "=r"(a) : "l"(p));
    return a;
}
__device__ __forceinline__ void cp16(uint32_t d, const void* s, int sz) {
    asm volatile("cp.async.cg.shared.global [%0], [%1], 16, %2;"
                 :: "r"(d), "l"(s), "r"(sz) : "memory");
}
__device__ __forceinline__ void cp_commit() {
    asm volatile("cp.async.commit_group;" ::: "memory");
}
template <int N> __device__ __forceinline__ void cp_wait() {
    asm volatile("cp.async.wait_group %0;" :: "n"(N) : "memory");
}
__device__ __forceinline__ void ldsm4(uint32_t* r, uint32_t a) {
    asm volatile("ldmatrix.sync.aligned.m8n8.x4.shared.b16 {%0,%1,%2,%3}, [%4];"
                 : "=r"(r[0]), "=r"(r[1]), "=r"(r[2]), "=r"(r[3]) : "r"(a));
}
__device__ __forceinline__ void mma16816(float* d, const uint32_t* a,
                                         const uint32_t* b) {
    asm volatile(
        "mma.sync.aligned.m16n8k16.row.col.f32.bf16.bf16.f32 "
        "{%0,%1,%2,%3}, {%4,%5,%6,%7}, {%8,%9}, {%0,%1,%2,%3};"
        : "+f"(d[0]), "+f"(d[1]), "+f"(d[2]), "+f"(d[3])
        : "r"(a[0]), "r"(a[1]), "r"(a[2]), "r"(a[3]), "r"(b[0]), "r"(b[1]));
}

// ------------------------------- GEMM kernel --------------------------------
// D[M, Ntot] = split3(A[M,K]) @ split3(B[Ntot,K])^T + bias; optional lrelu.
// BM=128, BN=256, BK=64. 8 warps: warp tile 64x64 (warp_m 2 x warp_n 4).
__global__ void __launch_bounds__(256, 1)
gemm_bf16x3(const __nv_bfloat16* __restrict__ Ahi, const __nv_bfloat16* __restrict__ Alo,
            const __nv_bfloat16* __restrict__ Bhi, const __nv_bfloat16* __restrict__ Blo,
            const float* __restrict__ bias,
            __nv_bfloat16* __restrict__ Chi, __nv_bfloat16* __restrict__ Clo,
            float* __restrict__ Yout,
            int K, int Ntot, int act, int f32out)
{
    extern __shared__ char sm[];
    const uint32_t sbase = smem_u32(sm);

    const int tid  = threadIdx.x;
    const int wid  = tid >> 5;
    const int lane = tid & 31;
    const int warp_m = wid & 1;        // 2 x 64 rows
    const int warp_n = wid >> 1;       // 4 x 64 cols
    const int m0 = blockIdx.y * 128;
    const int n0 = blockIdx.x * 256;

    float acc[4][8][4];
#pragma unroll
    for (int i = 0; i < 4; i++)
#pragma unroll
        for (int j = 0; j < 8; j++)
#pragma unroll
            for (int k = 0; k < 4; k++) acc[i][j][k] = 0.f;

    const int kn = K >> 6;             // BK = 64

    // ldmatrix per-lane offsets (bytes, within a stage)
    const uint32_t a_off = (uint32_t)((warp_m * 64 + (lane & 15)) * PITCH
                                      + (lane >> 4) * 16);
    const uint32_t b_off = (uint32_t)((warp_n * 64 + (lane & 7) + ((lane >> 4) << 3)) * PITCH
                                      + ((lane >> 3) & 1) * 16);

    // cp.async: A tiles 128x8 chunks (4/thread), B tiles 256x8 chunks (8/thread).
#define LOAD_STAGE(KS, BUF)                                                          \
    {                                                                                \
        const int k0_ = (KS) << 6;                                                   \
        const uint32_t sb_ = sbase + (BUF) * STAGE;                                  \
        _Pragma("unroll")                                                            \
        for (int j_ = 0; j_ < 4; j_++) {                                             \
            int slot_ = tid + j_ * 256;                                              \
            int row_ = slot_ >> 3;                                                   \
            int col_ = slot_ & 7;                                                    \
            uint32_t d_ = sb_ + (uint32_t)(row_ * PITCH + col_ * 16);                \
            size_t ga_ = (size_t)(m0 + row_) * K + k0_ + col_ * 8;                   \
            cp16(d_ + OFF_AH, Ahi + ga_, 16);                                        \
            cp16(d_ + OFF_AL, Alo + ga_, 16);                                        \
        }                                                                            \
        _Pragma("unroll")                                                            \
        for (int j_ = 0; j_ < 8; j_++) {                                             \
            int slot_ = tid + j_ * 256;                                              \
            int row_ = slot_ >> 3;                                                   \
            int col_ = slot_ & 7;                                                    \
            uint32_t d_ = sb_ + (uint32_t)(row_ * PITCH + col_ * 16);                \
            int n_ = n0 + row_;                                                      \
            int sz_ = (n_ < Ntot) ? 16 : 0;                                          \
            int nc_ = (n_ < Ntot) ? n_ : (Ntot - 1);                                 \
            size_t gb_ = (size_t)nc_ * K + k0_ + col_ * 8;                           \
            cp16(d_ + OFF_BH, Bhi + gb_, sz_);                                       \
            cp16(d_ + OFF_BL, Blo + gb_, sz_);                                       \
        }                                                                            \
    }

    LOAD_STAGE(0, 0); cp_commit();

    for (int ks = 0; ks < kn; ks++) {
        if (ks + 1 < kn) {
            LOAD_STAGE(ks + 1, (ks + 1) & 1); cp_commit(); cp_wait<1>();
        } else {
            cp_wait<0>();
        }
        __syncthreads();

        const uint32_t sb = sbase + (ks & 1) * STAGE;
#pragma unroll
        for (int kk = 0; kk < 4; kk++) {           // 4 x K16 per stage
            uint32_t ah[4][4], al[4][4];
#pragma unroll
            for (int mt = 0; mt < 4; mt++) {
                uint32_t o = a_off + (uint32_t)(mt * 16 * PITCH + kk * 32);
                ldsm4(ah[mt], sb + OFF_AH + o);
                ldsm4(al[mt], sb + OFF_AL + o);
            }
#pragma unroll
            for (int np = 0; np < 4; np++) {       // 4 x 16-col B panels
                uint32_t o = b_off + (uint32_t)(np * 16 * PITCH + kk * 32);
                uint32_t rh[4], rl[4];
                ldsm4(rh, sb + OFF_BH + o);
                ldsm4(rl, sb + OFF_BL + o);
#pragma unroll
                for (int mt = 0; mt < 4; mt++) {
                    mma16816(acc[mt][2 * np],     ah[mt], rh);
                    mma16816(acc[mt][2 * np],     ah[mt], rl);
                    mma16816(acc[mt][2 * np],     al[mt], rh);
                    mma16816(acc[mt][2 * np + 1], ah[mt], rh + 2);
                    mma16816(acc[mt][2 * np + 1], ah[mt], rl + 2);
                    mma16816(acc[mt][2 * np + 1], al[mt], rh + 2);
                }
            }
        }
        if (ks + 1 < kn) __syncthreads();   // protect buf before next overwrite
    }

    // ---- epilogue: bias + act, write split-bf16 or fp32 ----
    const int mrow = lane >> 2;
    const int ncol = (lane & 3) * 2;
#pragma unroll
    for (int mt = 0; mt < 4; mt++) {
#pragma unroll
        for (int nt = 0; nt < 8; nt++) {
            int n = n0 + warp_n * 64 + nt * 8 + ncol;
            if (n >= Ntot) continue;
            float bs0 = __ldg(bias + n);
            float bs1 = __ldg(bias + n + 1);
#pragma unroll
            for (int half = 0; half < 2; half++) {
                int m = m0 + warp_m * 64 + mt * 16 + mrow + half * 8;
                float v0 = acc[mt][nt][half * 2]     + bs0;
                float v1 = acc[mt][nt][half * 2 + 1] + bs1;
                if (act) {
                    v0 = v0 > 0.f ? v0 : 0.01f * v0;
                    v1 = v1 > 0.f ? v1 : 0.01f * v1;
                }
                if (f32out) {
                    *(float2*)(Yout + (size_t)m * Ntot + n) = make_float2(v0, v1);
                } else {
                    __nv_bfloat16 h0 = __float2bfloat16(v0);
                    __nv_bfloat16 h1 = __float2bfloat16(v1);
                    __nv_bfloat16 l0 = __float2bfloat16(v0 - __bfloat162float(h0));
                    __nv_bfloat16 l1 = __float2bfloat16(v1 - __bfloat162float(h1));
                    *(__nv_bfloat162*)(Chi + (size_t)m * Ntot + n) = __halves2bfloat162(h0, h1);
                    *(__nv_bfloat162*)(Clo + (size_t)m * Ntot + n) = __halves2bfloat162(l0, l1);
                }
            }
        }
    }
}

// --------------------------- split / transpose ------------------------------
__global__ void split_f32_kernel(const float* __restrict__ in,
                                 __nv_bfloat16* __restrict__ hi,
                                 __nv_bfloat16* __restrict__ lo, int n4)
{
    int i = blockIdx.x * blockDim.x + threadIdx.x;
    if (i < n4) {
        float4 v = ((const float4*)in)[i];
        __nv_bfloat16 h0 = __float2bfloat16(v.x), h1 = __float2bfloat16(v.y);
        __nv_bfloat16 h2 = __float2bfloat16(v.z), h3 = __float2bfloat16(v.w);
        __nv_bfloat16 l0 = __float2bfloat16(v.x - __bfloat162float(h0));
        __nv_bfloat16 l1 = __float2bfloat16(v.y - __bfloat162float(h1));
        __nv_bfloat16 l2 = __float2bfloat16(v.z - __bfloat162float(h2));
        __nv_bfloat16 l3 = __float2bfloat16(v.w - __bfloat162float(h3));
        ((__nv_bfloat162*)hi)[i * 2]     = __halves2bfloat162(h0, h1);
        ((__nv_bfloat162*)hi)[i * 2 + 1] = __halves2bfloat162(h2, h3);
        ((__nv_bfloat162*)lo)[i * 2]     = __halves2bfloat162(l0, l1);
        ((__nv_bfloat162*)lo)[i * 2 + 1] = __halves2bfloat162(l2, l3);
    }
}

// W[K,N] fp32 -> BT[N,K] bf16 hi/lo (transpose + split). Dims %32 == 0.
__global__ void wsplit_t_kernel(const float* __restrict__ W,
                                __nv_bfloat16* __restrict__ bth,
                                __nv_bfloat16* __restrict__ btl, int K, int N)
{
    __shared__ float t[32][33];
    const int n0 = blockIdx.x * 32, k0 = blockIdx.y * 32;
    const int tx = threadIdx.x, ty = threadIdx.y;
#pragma unroll
    for (int i = 0; i < 32; i += 8)
        t[ty + i][tx] = W[(size_t)(k0 + ty + i) * N + n0 + tx];
    __syncthreads();
#pragma unroll
    for (int i = 0; i < 32; i += 8) {
        float v = t[tx][ty + i];                 // element (k0+tx, n0+ty+i)
        __nv_bfloat16 h = __float2bfloat16(v);
        __nv_bfloat16 l = __float2bfloat16(v - __bfloat162float(h));
        size_t o = (size_t)(n0 + ty + i) * K + k0 + tx;
        bth[o] = h;
        btl[o] = l;
    }
}

// ------------------------------- scatter ------------------------------------
__global__ void scatter_tri(const float* __restrict__ y, float* __restrict__ out)
{
    __shared__ float tile[32][33];
    const int l0 = blockIdx.x * 32;
    const int b0 = blockIdx.y * 32;
    const int txi = threadIdx.x;
    const int tyi = threadIdx.y;

#pragma unroll
    for (int i = 0; i < 32; i += 8)
        tile[tyi + i][txi] = y[(size_t)(b0 + tyi + i) * LOUT + l0 + txi];
    __syncthreads();

#pragma unroll
    for (int i = 0; i < 32; i += 8) {
        int l = l0 + tyi + i;
        float disc = 16641.0f - 8.0f * (float)l;
        int r = (int)((129.0f - sqrtf(disc)) * 0.5f);
        if (r < 0) r = 0;
        if (r > 63) r = 63;
        while (r < 63 && (r + 1) * (129 - (r + 1)) / 2 <= l) r++;
        while (r > 0 && r * (129 - r) / 2 > l) r--;
        int c = 63 - (l - r * (129 - r) / 2);
        float v = tile[txi][tyi + i];            // transposed read
        if (r == c && v <= 0.f) v = -v;
        out[((size_t)(r * CPV + c)) * BATCH + b0 + txi] = v;
    }
}

// ------------------------------- launcher -----------------------------------
extern "C" void kernel_launch(void* const* d_in, const int* in_sizes, int n_in,
                              void* d_out, int out_size)
{
    // Identify inputs by element count (robust to metadata ordering).
    const float *x = 0, *W1 = 0, *W2 = 0, *W21 = 0, *W22 = 0, *W3 = 0;
    const float *b1 = 0, *b2 = 0, *b21 = 0, *b22 = 0, *b3 = 0;
    int nhh = 0, nbb = 0;
    for (int i = 0; i < n_in; i++) {
        const float* p = (const float*)d_in[i];
        switch (in_sizes[i]) {
            case 8388608: x  = p; break;
            case 2097152: W1 = p; break;
            case 4259840: W3 = p; break;
            case 2080:    b3 = p; break;
            case 4194304:
                if      (nhh == 0) W2  = p;
                else if (nhh == 1) W21 = p;
                else               W22 = p;
                nhh++; break;
            case 2048:
                if      (nbb == 0) b1  = p;
                else if (nbb == 1) b2  = p;
                else if (nbb == 2) b21 = p;
                else               b22 = p;
                nbb++; break;
            default: break;
        }
    }

    void *pAh0, *pAl0, *pAh1, *pAl1, *pW1h, *pW1l, *pW2h, *pW2l;
    void *pW21h, *pW21l, *pW22h, *pW22l, *pW3h, *pW3l, *pY;
    cudaGetSymbolAddress(&pAh0, g_Ah0);   cudaGetSymbolAddress(&pAl0, g_Al0);
    cudaGetSymbolAddress(&pAh1, g_Ah1);   cudaGetSymbolAddress(&pAl1, g_Al1);
    cudaGetSymbolAddress(&pW1h, g_W1h);   cudaGetSymbolAddress(&pW1l, g_W1l);
    cudaGetSymbolAddress(&pW2h, g_W2h);   cudaGetSymbolAddress(&pW2l, g_W2l);
    cudaGetSymbolAddress(&pW21h, g_W21h); cudaGetSymbolAddress(&pW21l, g_W21l);
    cudaGetSymbolAddress(&pW22h, g_W22h); cudaGetSymbolAddress(&pW22l, g_W22l);
    cudaGetSymbolAddress(&pW3h, g_W3h);   cudaGetSymbolAddress(&pW3l, g_W3l);
    cudaGetSymbolAddress(&pY, g_Y);
    __nv_bfloat16 *Ah0 = (__nv_bfloat16*)pAh0, *Al0 = (__nv_bfloat16*)pAl0;
    __nv_bfloat16 *Ah1 = (__nv_bfloat16*)pAh1, *Al1 = (__nv_bfloat16*)pAl1;
    __nv_bfloat16 *W1h = (__nv_bfloat16*)pW1h, *W1l = (__nv_bfloat16*)pW1l;
    __nv_bfloat16 *W2h = (__nv_bfloat16*)pW2h, *W2l = (__nv_bfloat16*)pW2l;
    __nv_bfloat16 *W21h = (__nv_bfloat16*)pW21h, *W21l = (__nv_bfloat16*)pW21l;
    __nv_bfloat16 *W22h = (__nv_bfloat16*)pW22h, *W22l = (__nv_bfloat16*)pW22l;
    __nv_bfloat16 *W3h = (__nv_bfloat16*)pW3h, *W3l = (__nv_bfloat16*)pW3l;
    float* Y = (float*)pY;

    cudaFuncSetAttribute(gemm_bf16x3,
                         cudaFuncAttributeMaxDynamicSharedMemorySize, SMEMSZ);

    // Split x; transpose+split weights.
    split_f32_kernel<<<(BATCH * DIN / 4 + 255) / 256, 256>>>(x, Ah0, Al0, BATCH * DIN / 4);
    dim3 tb(32, 8);
    wsplit_t_kernel<<<dim3(HID / 32, DIN / 32), tb>>>(W1, W1h, W1l, DIN, HID);
    wsplit_t_kernel<<<dim3(HID / 32, HID / 32), tb>>>(W2, W2h, W2l, HID, HID);
    wsplit_t_kernel<<<dim3(HID / 32, HID / 32), tb>>>(W21, W21h, W21l, HID, HID);
    wsplit_t_kernel<<<dim3(HID / 32, HID / 32), tb>>>(W22, W22h, W22l, HID, HID);
    wsplit_t_kernel<<<dim3(LOUT / 32, HID / 32), tb>>>(W3, W3h, W3l, HID, LOUT);

    // GEMM chain (HMMA tensor cores)
    dim3 blk(256);
    dim3 gH(HID / 256, BATCH / 128);                     // (8, 64)
    dim3 gL((LOUT + 255) / 256, BATCH / 128);            // (9, 64)
    gemm_bf16x3<<<gH, blk, SMEMSZ>>>(Ah0, Al0, W1h, W1l, b1, Ah1, Al1, 0, DIN, HID, 1, 0);
    gemm_bf16x3<<<gH, blk, SMEMSZ>>>(Ah1, Al1, W2h, W2l, b2, Ah0, Al0, 0, HID, HID, 1, 0);
    gemm_bf16x3<<<gH, blk, SMEMSZ>>>(Ah0, Al0, W21h, W21l, b21, Ah1, Al1, 0, HID, HID, 1, 0);
    gemm_bf16x3<<<gH, blk, SMEMSZ>>>(Ah1, Al1, W22h, W22l, b22, Ah0, Al0, 0, HID, HID, 1, 0);
    gemm_bf16x3<<<gL, blk, SMEMSZ>>>(Ah0, Al0, W3h, W3l, b3, 0, 0, Y, HID, LOUT, 0, 1);

    cudaMemsetAsync(d_out, 0, (size_t)out_size * sizeof(float), 0);
    dim3 gsc(LOUT / 32, BATCH / 32);
    dim3 bsc(32, 8);
    scatter_tri<<<gsc, bsc>>>(Y, (float*)d_out);
}

// round 10
// speedup vs baseline: 1.0029x; 1.0029x over previous
#include <cuda_runtime.h>
#include <cuda_bf16.h>
#include <cstdint>

// ============================================================================
// ModelR: x[8192,1024] -> (Linear+LeakyReLU) x4 -> Linear -> tri-scatter
// Round 10: R9 tiling (BM=128,BN=256,BK=64, 2-stage) with MMA issue reordered
// term-major: 4 independent accumulators between reuses (RAW distance 1 -> 8).
// Per-accumulator term order unchanged (hh->hl->lh) => rel_err must be
// bitwise identical (3.04346e-5). Launches reordered so ncu -s 5 captures
// the GEMM kernel instead of wsplit.
//   D = Ah*Bh + Ah*Bl + Al*Bh  (bf16 hi/lo split, fp32 accum, err ~2^-16)
// ============================================================================

#define BATCH 8192
#define DIN   1024
#define HID   2048
#define LOUT  2080
#define CPV   64

#define PITCH   144         // 128B payload (64 bf16) + 16B pad
#define OFF_AH  0
#define OFF_AL  18432       // 128 rows * 144B
#define OFF_BH  36864
#define OFF_BL  73728       // OFF_BH + 256 rows * 144B
#define STAGE   110592
#define NSTAGE  2
#define SMEMSZ  (NSTAGE * STAGE)   // 221184 B

// ------------------------- device scratch (no allocs) -----------------------
__device__ __nv_bfloat16 g_Ah0[(size_t)BATCH * HID];
__device__ __nv_bfloat16 g_Al0[(size_t)BATCH * HID];
__device__ __nv_bfloat16 g_Ah1[(size_t)BATCH * HID];
__device__ __nv_bfloat16 g_Al1[(size_t)BATCH * HID];
__device__ __nv_bfloat16 g_W1h[(size_t)HID * DIN];
__device__ __nv_bfloat16 g_W1l[(size_t)HID * DIN];
__device__ __nv_bfloat16 g_W2h[(size_t)HID * HID];
__device__ __nv_bfloat16 g_W2l[(size_t)HID * HID];
__device__ __nv_bfloat16 g_W21h[(size_t)HID * HID];
__device__ __nv_bfloat16 g_W21l[(size_t)HID * HID];
__device__ __nv_bfloat16 g_W22h[(size_t)HID * HID];
__device__ __nv_bfloat16 g_W22l[(size_t)HID * HID];
__device__ __nv_bfloat16 g_W3h[(size_t)LOUT * HID];
__device__ __nv_bfloat16 g_W3l[(size_t)LOUT * HID];
__device__ float         g_Y[(size_t)BATCH * LOUT];

// ------------------------------ PTX helpers ---------------------------------
__device__ __forceinline__ uint32_t smem_u32(const void* p) {
    uint32_t a;
    asm("{ .reg .u64 t; cvta.to.shared.u64 t, %1; cvt.u32.u64 %0, t; }"
        : "=r"(a) : "l"(p));
    return a;
}
__device__ __forceinline__ void cp16(uint32_t d, const void* s, int sz) {
    asm volatile("cp.async.cg.shared.global [%0], [%1], 16, %2;"
                 :: "r"(d), "l"(s), "r"(sz) : "memory");
}
__device__ __forceinline__ void cp_commit() {
    asm volatile("cp.async.commit_group;" ::: "memory");
}
template <int N> __device__ __forceinline__ void cp_wait() {
    asm volatile("cp.async.wait_group %0;" :: "n"(N) : "memory");
}
__device__ __forceinline__ void ldsm4(uint32_t* r, uint32_t a) {
    asm volatile("ldmatrix.sync.aligned.m8n8.x4.shared.b16 {%0,%1,%2,%3}, [%4];"
                 : "=r"(r[0]), "=r"(r[1]), "=r"(r[2]), "=r"(r[3]) : "r"(a));
}
__device__ __forceinline__ void mma16816(float* d, const uint32_t* a,
                                         const uint32_t* b) {
    asm volatile(
        "mma.sync.aligned.m16n8k16.row.col.f32.bf16.bf16.f32 "
        "{%0,%1,%2,%3}, {%4,%5,%6,%7}, {%8,%9}, {%0,%1,%2,%3};"
        : "+f"(d[0]), "+f"(d[1]), "+f"(d[2]), "+f"(d[3])
        : "r"(a[0]), "r"(a[1]), "r"(a[2]), "r"(a[3]), "r"(b[0]), "r"(b[1]));
}

// ------------------------------- GEMM kernel --------------------------------
// D[M, Ntot] = split3(A[M,K]) @ split3(B[Ntot,K])^T + bias; optional lrelu.
// BM=128, BN=256, BK=64. 8 warps: warp tile 64x64 (warp_m 2 x warp_n 4).
__global__ void __launch_bounds__(256, 1)
gemm_bf16x3(const __nv_bfloat16* __restrict__ Ahi, const __nv_bfloat16* __restrict__ Alo,
            const __nv_bfloat16* __restrict__ Bhi, const __nv_bfloat16* __restrict__ Blo,
            const float* __restrict__ bias,
            __nv_bfloat16* __restrict__ Chi, __nv_bfloat16* __restrict__ Clo,
            float* __restrict__ Yout,
            int K, int Ntot, int act, int f32out)
{
    extern __shared__ char sm[];
    const uint32_t sbase = smem_u32(sm);

    const int tid  = threadIdx.x;
    const int wid  = tid >> 5;
    const int lane = tid & 31;
    const int warp_m = wid & 1;        // 2 x 64 rows
    const int warp_n = wid >> 1;       // 4 x 64 cols
    const int m0 = blockIdx.y * 128;
    const int n0 = blockIdx.x * 256;

    float acc[4][8][4];
#pragma unroll
    for (int i = 0; i < 4; i++)
#pragma unroll
        for (int j = 0; j < 8; j++)
#pragma unroll
            for (int k = 0; k < 4; k++) acc[i][j][k] = 0.f;

    const int kn = K >> 6;             // BK = 64

    // ldmatrix per-lane offsets (bytes, within a stage)
    const uint32_t a_off = (uint32_t)((warp_m * 64 + (lane & 15)) * PITCH
                                      + (lane >> 4) * 16);
    const uint32_t b_off = (uint32_t)((warp_n * 64 + (lane & 7) + ((lane >> 4) << 3)) * PITCH
                                      + ((lane >> 3) & 1) * 16);

    // cp.async: A tiles 128x8 chunks (4/thread), B tiles 256x8 chunks (8/thread).
#define LOAD_STAGE(KS, BUF)                                                          \
    {                                                                                \
        const int k0_ = (KS) << 6;                                                   \
        const uint32_t sb_ = sbase + (BUF) * STAGE;                                  \
        _Pragma("unroll")                                                            \
        for (int j_ = 0; j_ < 4; j_++) {                                             \
            int slot_ = tid + j_ * 256;                                              \
            int row_ = slot_ >> 3;                                                   \
            int col_ = slot_ & 7;                                                    \
            uint32_t d_ = sb_ + (uint32_t)(row_ * PITCH + col_ * 16);                \
            size_t ga_ = (size_t)(m0 + row_) * K + k0_ + col_ * 8;                   \
            cp16(d_ + OFF_AH, Ahi + ga_, 16);                                        \
            cp16(d_ + OFF_AL, Alo + ga_, 16);                                        \
        }                                                                            \
        _Pragma("unroll")                                                            \
        for (int j_ = 0; j_ < 8; j_++) {                                             \
            int slot_ = tid + j_ * 256;                                              \
            int row_ = slot_ >> 3;                                                   \
            int col_ = slot_ & 7;                                                    \
            uint32_t d_ = sb_ + (uint32_t)(row_ * PITCH + col_ * 16);                \
            int n_ = n0 + row_;                                                      \
            int sz_ = (n_ < Ntot) ? 16 : 0;                                          \
            int nc_ = (n_ < Ntot) ? n_ : (Ntot - 1);                                 \
            size_t gb_ = (size_t)nc_ * K + k0_ + col_ * 8;                           \
            cp16(d_ + OFF_BH, Bhi + gb_, sz_);                                       \
            cp16(d_ + OFF_BL, Blo + gb_, sz_);                                       \
        }                                                                            \
    }

    LOAD_STAGE(0, 0); cp_commit();

    for (int ks = 0; ks < kn; ks++) {
        if (ks + 1 < kn) {
            LOAD_STAGE(ks + 1, (ks + 1) & 1); cp_commit(); cp_wait<1>();
        } else {
            cp_wait<0>();
        }
        __syncthreads();

        const uint32_t sb = sbase + (ks & 1) * STAGE;
#pragma unroll
        for (int kk = 0; kk < 4; kk++) {           // 4 x K16 per stage
            uint32_t ah[4][4], al[4][4];
#pragma unroll
            for (int mt = 0; mt < 4; mt++) {
                uint32_t o = a_off + (uint32_t)(mt * 16 * PITCH + kk * 32);
                ldsm4(ah[mt], sb + OFF_AH + o);
                ldsm4(al[mt], sb + OFF_AL + o);
            }
#pragma unroll
            for (int np = 0; np < 4; np++) {       // 4 x 16-col B panels
                uint32_t o = b_off + (uint32_t)(np * 16 * PITCH + kk * 32);
                uint32_t rh[4], rl[4];
                ldsm4(rh, sb + OFF_BH + o);
                ldsm4(rl, sb + OFF_BL + o);
                // Term-major issue: 4 independent accumulators between
                // reuses (RAW distance 8). Per-acc term order stays
                // hh -> hl -> lh (bitwise-identical result to R9).
#pragma unroll
                for (int mt = 0; mt < 4; mt++)
                    mma16816(acc[mt][2 * np],     ah[mt], rh);
#pragma unroll
                for (int mt = 0; mt < 4; mt++)
                    mma16816(acc[mt][2 * np + 1], ah[mt], rh + 2);
#pragma unroll
                for (int mt = 0; mt < 4; mt++)
                    mma16816(acc[mt][2 * np],     ah[mt], rl);
#pragma unroll
                for (int mt = 0; mt < 4; mt++)
                    mma16816(acc[mt][2 * np + 1], ah[mt], rl + 2);
#pragma unroll
                for (int mt = 0; mt < 4; mt++)
                    mma16816(acc[mt][2 * np],     al[mt], rh);
#pragma unroll
                for (int mt = 0; mt < 4; mt++)
                    mma16816(acc[mt][2 * np + 1], al[mt], rh + 2);
            }
        }
        if (ks + 1 < kn) __syncthreads();   // protect buf before next overwrite
    }

    // ---- epilogue: bias + act, write split-bf16 or fp32 ----
    const int mrow = lane >> 2;
    const int ncol = (lane & 3) * 2;
#pragma unroll
    for (int mt = 0; mt < 4; mt++) {
#pragma unroll
        for (int nt = 0; nt < 8; nt++) {
            int n = n0 + warp_n * 64 + nt * 8 + ncol;
            if (n >= Ntot) continue;
            float bs0 = __ldg(bias + n);
            float bs1 = __ldg(bias + n + 1);
#pragma unroll
            for (int half = 0; half < 2; half++) {
                int m = m0 + warp_m * 64 + mt * 16 + mrow + half * 8;
                float v0 = acc[mt][nt][half * 2]     + bs0;
                float v1 = acc[mt][nt][half * 2 + 1] + bs1;
                if (act) {
                    v0 = v0 > 0.f ? v0 : 0.01f * v0;
                    v1 = v1 > 0.f ? v1 : 0.01f * v1;
                }
                if (f32out) {
                    *(float2*)(Yout + (size_t)m * Ntot + n) = make_float2(v0, v1);
                } else {
                    __nv_bfloat16 h0 = __float2bfloat16(v0);
                    __nv_bfloat16 h1 = __float2bfloat16(v1);
                    __nv_bfloat16 l0 = __float2bfloat16(v0 - __bfloat162float(h0));
                    __nv_bfloat16 l1 = __float2bfloat16(v1 - __bfloat162float(h1));
                    *(__nv_bfloat162*)(Chi + (size_t)m * Ntot + n) = __halves2bfloat162(h0, h1);
                    *(__nv_bfloat162*)(Clo + (size_t)m * Ntot + n) = __halves2bfloat162(l0, l1);
                }
            }
        }
    }
}

// --------------------------- split / transpose ------------------------------
__global__ void split_f32_kernel(const float* __restrict__ in,
                                 __nv_bfloat16* __restrict__ hi,
                                 __nv_bfloat16* __restrict__ lo, int n4)
{
    int i = blockIdx.x * blockDim.x + threadIdx.x;
    if (i < n4) {
        float4 v = ((const float4*)in)[i];
        __nv_bfloat16 h0 = __float2bfloat16(v.x), h1 = __float2bfloat16(v.y);
        __nv_bfloat16 h2 = __float2bfloat16(v.z), h3 = __float2bfloat16(v.w);
        __nv_bfloat16 l0 = __float2bfloat16(v.x - __bfloat162float(h0));
        __nv_bfloat16 l1 = __float2bfloat16(v.y - __bfloat162float(h1));
        __nv_bfloat16 l2 = __float2bfloat16(v.z - __bfloat162float(h2));
        __nv_bfloat16 l3 = __float2bfloat16(v.w - __bfloat162float(h3));
        ((__nv_bfloat162*)hi)[i * 2]     = __halves2bfloat162(h0, h1);
        ((__nv_bfloat162*)hi)[i * 2 + 1] = __halves2bfloat162(h2, h3);
        ((__nv_bfloat162*)lo)[i * 2]     = __halves2bfloat162(l0, l1);
        ((__nv_bfloat162*)lo)[i * 2 + 1] = __halves2bfloat162(l2, l3);
    }
}

// W[K,N] fp32 -> BT[N,K] bf16 hi/lo (transpose + split). Dims %32 == 0.
__global__ void wsplit_t_kernel(const float* __restrict__ W,
                                __nv_bfloat16* __restrict__ bth,
                                __nv_bfloat16* __restrict__ btl, int K, int N)
{
    __shared__ float t[32][33];
    const int n0 = blockIdx.x * 32, k0 = blockIdx.y * 32;
    const int tx = threadIdx.x, ty = threadIdx.y;
#pragma unroll
    for (int i = 0; i < 32; i += 8)
        t[ty + i][tx] = W[(size_t)(k0 + ty + i) * N + n0 + tx];
    __syncthreads();
#pragma unroll
    for (int i = 0; i < 32; i += 8) {
        float v = t[tx][ty + i];                 // element (k0+tx, n0+ty+i)
        __nv_bfloat16 h = __float2bfloat16(v);
        __nv_bfloat16 l = __float2bfloat16(v - __bfloat162float(h));
        size_t o = (size_t)(n0 + ty + i) * K + k0 + tx;
        bth[o] = h;
        btl[o] = l;
    }
}

// ------------------------------- scatter ------------------------------------
__global__ void scatter_tri(const float* __restrict__ y, float* __restrict__ out)
{
    __shared__ float tile[32][33];
    const int l0 = blockIdx.x * 32;
    const int b0 = blockIdx.y * 32;
    const int txi = threadIdx.x;
    const int tyi = threadIdx.y;

#pragma unroll
    for (int i = 0; i < 32; i += 8)
        tile[tyi + i][txi] = y[(size_t)(b0 + tyi + i) * LOUT + l0 + txi];
    __syncthreads();

#pragma unroll
    for (int i = 0; i < 32; i += 8) {
        int l = l0 + tyi + i;
        float disc = 16641.0f - 8.0f * (float)l;
        int r = (int)((129.0f - sqrtf(disc)) * 0.5f);
        if (r < 0) r = 0;
        if (r > 63) r = 63;
        while (r < 63 && (r + 1) * (129 - (r + 1)) / 2 <= l) r++;
        while (r > 0 && r * (129 - r) / 2 > l) r--;
        int c = 63 - (l - r * (129 - r) / 2);
        float v = tile[txi][tyi + i];            // transposed read
        if (r == c && v <= 0.f) v = -v;
        out[((size_t)(r * CPV + c)) * BATCH + b0 + txi] = v;
    }
}

// ------------------------------- launcher -----------------------------------
extern "C" void kernel_launch(void* const* d_in, const int* in_sizes, int n_in,
                              void* d_out, int out_size)
{
    // Identify inputs by element count (robust to metadata ordering).
    const float *x = 0, *W1 = 0, *W2 = 0, *W21 = 0, *W22 = 0, *W3 = 0;
    const float *b1 = 0, *b2 = 0, *b21 = 0, *b22 = 0, *b3 = 0;
    int nhh = 0, nbb = 0;
    for (int i = 0; i < n_in; i++) {
        const float* p = (const float*)d_in[i];
        switch (in_sizes[i]) {
            case 8388608: x  = p; break;
            case 2097152: W1 = p; break;
            case 4259840: W3 = p; break;
            case 2080:    b3 = p; break;
            case 4194304:
                if      (nhh == 0) W2  = p;
                else if (nhh == 1) W21 = p;
                else               W22 = p;
                nhh++; break;
            case 2048:
                if      (nbb == 0) b1  = p;
                else if (nbb == 1) b2  = p;
                else if (nbb == 2) b21 = p;
                else               b22 = p;
                nbb++; break;
            default: break;
        }
    }

    void *pAh0, *pAl0, *pAh1, *pAl1, *pW1h, *pW1l, *pW2h, *pW2l;
    void *pW21h, *pW21l, *pW22h, *pW22l, *pW3h, *pW3l, *pY;
    cudaGetSymbolAddress(&pAh0, g_Ah0);   cudaGetSymbolAddress(&pAl0, g_Al0);
    cudaGetSymbolAddress(&pAh1, g_Ah1);   cudaGetSymbolAddress(&pAl1, g_Al1);
    cudaGetSymbolAddress(&pW1h, g_W1h);   cudaGetSymbolAddress(&pW1l, g_W1l);
    cudaGetSymbolAddress(&pW2h, g_W2h);   cudaGetSymbolAddress(&pW2l, g_W2l);
    cudaGetSymbolAddress(&pW21h, g_W21h); cudaGetSymbolAddress(&pW21l, g_W21l);
    cudaGetSymbolAddress(&pW22h, g_W22h); cudaGetSymbolAddress(&pW22l, g_W22l);
    cudaGetSymbolAddress(&pW3h, g_W3h);   cudaGetSymbolAddress(&pW3l, g_W3l);
    cudaGetSymbolAddress(&pY, g_Y);
    __nv_bfloat16 *Ah0 = (__nv_bfloat16*)pAh0, *Al0 = (__nv_bfloat16*)pAl0;
    __nv_bfloat16 *Ah1 = (__nv_bfloat16*)pAh1, *Al1 = (__nv_bfloat16*)pAl1;
    __nv_bfloat16 *W1h = (__nv_bfloat16*)pW1h, *W1l = (__nv_bfloat16*)pW1l;
    __nv_bfloat16 *W2h = (__nv_bfloat16*)pW2h, *W2l = (__nv_bfloat16*)pW2l;
    __nv_bfloat16 *W21h = (__nv_bfloat16*)pW21h, *W21l = (__nv_bfloat16*)pW21l;
    __nv_bfloat16 *W22h = (__nv_bfloat16*)pW22h, *W22l = (__nv_bfloat16*)pW22l;
    __nv_bfloat16 *W3h = (__nv_bfloat16*)pW3h, *W3l = (__nv_bfloat16*)pW3l;
    float* Y = (float*)pY;

    cudaFuncSetAttribute(gemm_bf16x3,
                         cudaFuncAttributeMaxDynamicSharedMemorySize, SMEMSZ);

    dim3 tb(32, 8);
    dim3 blk(256);
    dim3 gH(HID / 256, BATCH / 128);                     // (8, 64)
    dim3 gL((LOUT + 255) / 256, BATCH / 128);            // (9, 64)

    // Launch order chosen so ncu (-s 5 -c 1) captures gemm_bf16x3 (index 5):
    //   0: split_f32, 1-4: wsplit W1/W2/W21/W22, 5: gemm1, 6-8: gemm2-4,
    //   9: wsplit W3, 10: gemm5, 11: memset, 12: scatter.
    split_f32_kernel<<<(BATCH * DIN / 4 + 255) / 256, 256>>>(x, Ah0, Al0, BATCH * DIN / 4);
    wsplit_t_kernel<<<dim3(HID / 32, DIN / 32), tb>>>(W1, W1h, W1l, DIN, HID);
    wsplit_t_kernel<<<dim3(HID / 32, HID / 32), tb>>>(W2, W2h, W2l, HID, HID);
    wsplit_t_kernel<<<dim3(HID / 32, HID / 32), tb>>>(W21, W21h, W21l, HID, HID);
    wsplit_t_kernel<<<dim3(HID / 32, HID / 32), tb>>>(W22, W22h, W22l, HID, HID);

    gemm_bf16x3<<<gH, blk, SMEMSZ>>>(Ah0, Al0, W1h, W1l, b1, Ah1, Al1, 0, DIN, HID, 1, 0);
    gemm_bf16x3<<<gH, blk, SMEMSZ>>>(Ah1, Al1, W2h, W2l, b2, Ah0, Al0, 0, HID, HID, 1, 0);
    gemm_bf16x3<<<gH, blk, SMEMSZ>>>(Ah0, Al0, W21h, W21l, b21, Ah1, Al1, 0, HID, HID, 1, 0);
    gemm_bf16x3<<<gH, blk, SMEMSZ>>>(Ah1, Al1, W22h, W22l, b22, Ah0, Al0, 0, HID, HID, 1, 0);

    wsplit_t_kernel<<<dim3(LOUT / 32, HID / 32), tb>>>(W3, W3h, W3l, HID, LOUT);
    gemm_bf16x3<<<gL, blk, SMEMSZ>>>(Ah0, Al0, W3h, W3l, b3, 0, 0, Y, HID, LOUT, 0, 1);

    cudaMemsetAsync(d_out, 0, (size_t)out_size * sizeof(float), 0);
    dim3 gsc(LOUT / 32, BATCH / 32);
    dim3 bsc(32, 8);
    scatter_tri<<<gsc, bsc>>>(Y, (float*)d_out);
}